// round 10
// baseline (speedup 1.0000x reference)
#include <cuda_runtime.h>

// ---------------- problem constants ----------------
#define N_NODES  50000
#define N_EDGES  640000
#define N_GRAPHS 64
#define IN_DIM   128
#define HID      256
#define HID2     128   // HID/2
#define OUT_DIM  4

// ---------------- scratch (static device arrays; no allocation) ----------------
// RULE: these symbols are ONLY referenced inside device code; never passed as
// kernel arguments from host (host shadow address + ATS = silent wrong buffer).
__device__ float  g_dinv[N_NODES];                 // rsqrt(deg+1)
__device__ int    g_count [N_NODES];               // in-degree histogram
__device__ int    g_cursor[N_NODES];               // CSR fill cursors
__device__ int    g_rowptr[N_NODES + 1];           // CSR row pointers (by dst)
__device__ int    g_esrc [N_EDGES];                // CSR: src node per slot
__device__ float  g_enorm[N_EDGES];                // CSR: dinv[s]*dinv[d] per slot
__device__ float4 g_agg1[N_NODES * (IN_DIM / 4)];  // aggregated x      [N,128]
__device__ float  g_h1 [N_NODES * HID];            // relu(agg1@W1+b1)  [N,256]
__device__ float4 g_m2  [N_NODES * (HID2 / 4)];    // h1@W2             [N,128]
__device__ float4 g_agg2[N_NODES * (HID2 / 4)];    // aggregated m2     [N,128]
__device__ float  g_pool[N_GRAPHS * HID2];         // per-graph sums
__device__ float  g_cnt [N_GRAPHS];                // per-graph counts
__device__ int    g_idx64;                         // 1 if index arrays are int64

// ---------------- helpers ----------------
__device__ __forceinline__ void red_add_v4(float* addr, float4 v) {
    asm volatile("red.global.add.v4.f32 [%0], {%1,%2,%3,%4};"
                 :: "l"(addr), "f"(v.x), "f"(v.y), "f"(v.z), "f"(v.w)
                 : "memory");
}

__device__ __forceinline__ int get_idx(const void* p, int i, int is64) {
    long long v;
    if (is64) v = __ldg(((const long long*)p) + i);
    else      v = __ldg(((const int*)p) + i);
    return (int)v;
}

__device__ __forceinline__ unsigned f2tf32(float f) {
    unsigned r;
    asm("cvt.rna.tf32.f32 %0, %1;" : "=r"(r) : "f"(f));
    return r;
}

// m16n8k8 tf32 MMA, fp32 accumulate (D += A*B), row.col
__device__ __forceinline__ void mma_tf32(float* d, const unsigned* a, const unsigned* b) {
    asm volatile(
        "mma.sync.aligned.m16n8k8.row.col.f32.tf32.tf32.f32 "
        "{%0,%1,%2,%3}, {%4,%5,%6,%7}, {%8,%9}, {%0,%1,%2,%3};"
        : "+f"(d[0]), "+f"(d[1]), "+f"(d[2]), "+f"(d[3])
        : "r"(a[0]), "r"(a[1]), "r"(a[2]), "r"(a[3]), "r"(b[0]), "r"(b[1]));
}

// ---------------- index dtype detection ----------------
__global__ void k_detect(const int* p) {
    int lane = threadIdx.x;
    int nz = 0;
    for (int i = lane; i < 4096; i += 32)
        if (p[2 * i + 1] != 0) nz = 1;
    unsigned m = __ballot_sync(0xffffffffu, nz);
    if (lane == 0) g_idx64 = (m == 0u) ? 1 : 0;
}

// ---------------- CSR build ----------------
__global__ void k_zero_csr() {
    int i = blockIdx.x * blockDim.x + threadIdx.x;
    if (i < N_NODES) g_count[i] = 0;
}

__global__ void k_hist(const void* __restrict__ dst) {
    int e = blockIdx.x * blockDim.x + threadIdx.x;
    if (e < N_EDGES) {
        int d = get_idx(dst, e, g_idx64);
        if ((unsigned)d < (unsigned)N_NODES) atomicAdd(&g_count[d], 1);
    }
}

// single block, 1024 threads: rowptr = exclusive scan of count,
// dinv = rsqrt(count+1), cursor = 0.
__global__ void __launch_bounds__(1024) k_scan() {
    __shared__ int part[1024];
    const int CH = (N_NODES + 1023) / 1024;       // 49
    int t = threadIdx.x;
    int b = t * CH; if (b > N_NODES) b = N_NODES;
    int e = b + CH; if (e > N_NODES) e = N_NODES;
    int s = 0;
    for (int i = b; i < e; i++) s += g_count[i];
    part[t] = s;
    __syncthreads();
    // Hillis-Steele inclusive scan
    for (int d = 1; d < 1024; d <<= 1) {
        int u = (t >= d) ? part[t - d] : 0;
        __syncthreads();
        part[t] += u;
        __syncthreads();
    }
    int run = part[t] - s;                        // exclusive offset
    for (int i = b; i < e; i++) {
        g_rowptr[i] = run;
        int c = g_count[i];
        run += c;
        g_dinv[i]   = rsqrtf((float)c + 1.0f);
        g_cursor[i] = 0;
    }
    if (t == 1023) g_rowptr[N_NODES] = part[1023];
}

__global__ void k_fill(const void* __restrict__ src, const void* __restrict__ dst) {
    int e = blockIdx.x * blockDim.x + threadIdx.x;
    if (e >= N_EDGES) return;
    int is64 = g_idx64;
    int s = get_idx(src, e, is64);
    int d = get_idx(dst, e, is64);
    if ((unsigned)s >= (unsigned)N_NODES || (unsigned)d >= (unsigned)N_NODES) return;
    int pos = g_rowptr[d] + atomicAdd(&g_cursor[d], 1);
    g_esrc [pos] = s;
    g_enorm[pos] = g_dinv[s] * g_dinv[d];
}

// ---------------- CSR gather aggregation ----------------
// One warp per destination node; lane j owns float4 column j.
// agg[d] = dinv[d]^2 * feat[d] + sum_{nbr} norm * feat[src]
__device__ __forceinline__ void gather_body(const float4* __restrict__ feat,
                                            float4* __restrict__ agg) {
    int wid = (blockIdx.x * blockDim.x + threadIdx.x) >> 5;
    if (wid >= N_NODES) return;
    int j = threadIdx.x & 31;
    float di = g_dinv[wid];
    float4 v0 = feat[(size_t)wid * 32 + j];
    float s2 = di * di;
    float4 acc = make_float4(v0.x * s2, v0.y * s2, v0.z * s2, v0.w * s2);

    int i   = g_rowptr[wid];
    int end = g_rowptr[wid + 1];
    for (; i + 1 < end; i += 2) {
        int   s0 = __ldg(&g_esrc[i]),      s1 = __ldg(&g_esrc[i + 1]);
        float w0 = __ldg(&g_enorm[i]),     w1 = __ldg(&g_enorm[i + 1]);
        float4 a = feat[(size_t)s0 * 32 + j];
        float4 b = feat[(size_t)s1 * 32 + j];
        acc.x += w0 * a.x + w1 * b.x;
        acc.y += w0 * a.y + w1 * b.y;
        acc.z += w0 * a.z + w1 * b.z;
        acc.w += w0 * a.w + w1 * b.w;
    }
    if (i < end) {
        int   s0 = __ldg(&g_esrc[i]);
        float w0 = __ldg(&g_enorm[i]);
        float4 a = feat[(size_t)s0 * 32 + j];
        acc.x += w0 * a.x; acc.y += w0 * a.y;
        acc.z += w0 * a.z; acc.w += w0 * a.w;
    }
    agg[(size_t)wid * 32 + j] = acc;
}

__global__ void k_gather1(const float4* __restrict__ x) { gather_body(x, g_agg1); }
__global__ void k_gather2()                             { gather_body(g_m2, g_agg2); }

// ---------------- GEMM via mma.sync m16n8k8 tf32 (fp32 accumulate) ----------------
template <int KDIM, int NDIM, bool RELU_BIAS>
__device__ __forceinline__ void gemm_mma_body(const float* __restrict__ A,
                                              const float* __restrict__ B,
                                              const float* __restrict__ bias,
                                              float* __restrict__ C) {
    constexpr int BM = 128, BN = 128, BK = 32;
    constexpr int ASTR = 36;
    constexpr int BSTR = 136;
    __shared__ unsigned As[BM * ASTR];
    __shared__ unsigned Bs[BK * BSTR];

    const int t    = threadIdx.x;
    const int lane = t & 31;
    const int w    = t >> 5;
    const int mw   = w & 3;
    const int nw   = w >> 2;
    const int g    = lane >> 2;
    const int tg   = lane & 3;
    const int cRow = blockIdx.y * BM;
    const int cCol = blockIdx.x * BN;

    float acc[2][8][4];
    #pragma unroll
    for (int mt = 0; mt < 2; mt++)
        #pragma unroll
        for (int nt = 0; nt < 8; nt++)
            #pragma unroll
            for (int i = 0; i < 4; i++) acc[mt][nt][i] = 0.0f;

    for (int k0 = 0; k0 < KDIM; k0 += BK) {
        #pragma unroll
        for (int i = 0; i < 4; i++) {
            int f   = t + 256 * i;
            int row = f >> 3;
            int c4  = f & 7;
            float4 v = make_float4(0.f, 0.f, 0.f, 0.f);
            if (cRow + row < N_NODES)
                v = *(const float4*)(A + (size_t)(cRow + row) * KDIM + k0 + c4 * 4);
            uint4 u = make_uint4(f2tf32(v.x), f2tf32(v.y), f2tf32(v.z), f2tf32(v.w));
            *(uint4*)&As[row * ASTR + c4 * 4] = u;
        }
        #pragma unroll
        for (int i = 0; i < 4; i++) {
            int f   = t + 256 * i;
            int row = f >> 5;
            int c4  = f & 31;
            float4 v = *(const float4*)(B + (size_t)(k0 + row) * NDIM + cCol + c4 * 4);
            uint4 u = make_uint4(f2tf32(v.x), f2tf32(v.y), f2tf32(v.z), f2tf32(v.w));
            *(uint4*)&Bs[row * BSTR + c4 * 4] = u;
        }
        __syncthreads();

        #pragma unroll
        for (int kk = 0; kk < BK; kk += 8) {
            unsigned a[2][4];
            #pragma unroll
            for (int mt = 0; mt < 2; mt++) {
                int r0 = mw * 32 + mt * 16 + g;
                a[mt][0] = As[r0 * ASTR + kk + tg];
                a[mt][1] = As[(r0 + 8) * ASTR + kk + tg];
                a[mt][2] = As[r0 * ASTR + kk + tg + 4];
                a[mt][3] = As[(r0 + 8) * ASTR + kk + tg + 4];
            }
            #pragma unroll
            for (int nt = 0; nt < 8; nt++) {
                unsigned b[2];
                int c0 = nw * 64 + nt * 8 + g;
                b[0] = Bs[(kk + tg)     * BSTR + c0];
                b[1] = Bs[(kk + tg + 4) * BSTR + c0];
                mma_tf32(acc[0][nt], a[0], b);
                mma_tf32(acc[1][nt], a[1], b);
            }
        }
        __syncthreads();
    }

    #pragma unroll
    for (int mt = 0; mt < 2; mt++) {
        int rBase = cRow + mw * 32 + mt * 16 + g;
        #pragma unroll
        for (int nt = 0; nt < 8; nt++) {
            int c = cCol + nw * 64 + nt * 8 + 2 * tg;
            float2 lo = make_float2(acc[mt][nt][0], acc[mt][nt][1]);
            float2 hi = make_float2(acc[mt][nt][2], acc[mt][nt][3]);
            if (RELU_BIAS) {
                float2 bb = *(const float2*)(bias + c);
                lo.x = fmaxf(lo.x + bb.x, 0.f); lo.y = fmaxf(lo.y + bb.y, 0.f);
                hi.x = fmaxf(hi.x + bb.x, 0.f); hi.y = fmaxf(hi.y + bb.y, 0.f);
            }
            if (rBase < N_NODES)
                *(float2*)(C + (size_t)rBase * NDIM + c) = lo;
            if (rBase + 8 < N_NODES)
                *(float2*)(C + (size_t)(rBase + 8) * NDIM + c) = hi;
        }
    }
}

__global__ void __launch_bounds__(256) k_gemm1(const float* __restrict__ W1,
                                               const float* __restrict__ b1) {
    gemm_mma_body<IN_DIM, HID, true>((const float*)g_agg1, W1, b1, g_h1);
}

__global__ void __launch_bounds__(256) k_gemm2(const float* __restrict__ W2) {
    gemm_mma_body<HID, HID2, false>(g_h1, W2, nullptr, (float*)g_m2);
}

// ---------------- pooling ----------------
__global__ void k_zero_pool() {
    int i = blockIdx.x * blockDim.x + threadIdx.x;
    if (i < N_GRAPHS * HID2) g_pool[i] = 0.0f;
    if (i < N_GRAPHS) g_cnt[i] = 0.0f;
}

__global__ void k_pool(const void* __restrict__ batch, const float* __restrict__ b2) {
    int t = blockIdx.x * blockDim.x + threadIdx.x;
    if (t >= N_NODES * 32) return;
    int node = t >> 5;
    int j    = t & 31;
    int b    = get_idx(batch, node, g_idx64);
    if ((unsigned)b >= (unsigned)N_GRAPHS) return;
    float4 v  = g_agg2[t];
    float4 bb = ((const float4*)b2)[j];
    v.x = fmaxf(v.x + bb.x, 0.f);
    v.y = fmaxf(v.y + bb.y, 0.f);
    v.z = fmaxf(v.z + bb.z, 0.f);
    v.w = fmaxf(v.w + bb.w, 0.f);
    red_add_v4(&g_pool[b * HID2 + j * 4], v);
    if (j == 0) atomicAdd(&g_cnt[b], 1.0f);
}

__global__ void k_out(const float* __restrict__ Wfc, const float* __restrict__ bfc,
                      float* __restrict__ out) {
    int t = threadIdx.x;
    if (t >= N_GRAPHS * OUT_DIM) return;
    int g = t >> 2;
    int o = t & 3;
    float inv = 1.0f / fmaxf(g_cnt[g], 1.0f);
    float s = 0.0f;
    #pragma unroll 16
    for (int k = 0; k < HID2; k++)
        s = fmaf(g_pool[g * HID2 + k], Wfc[k * OUT_DIM + o], s);
    out[t] = s * inv + bfc[o];
}

// ---------------- launch ----------------
extern "C" void kernel_launch(void* const* d_in, const int* in_sizes, int n_in,
                              void* d_out, int out_size) {
    int ix = -1, isrc = -1, idst = -1, ibatch = -1, iW1 = -1, iW2 = -1;
    int ib1 = -1, ib2 = -1, iWfc = -1, ibfc = -1;
    for (int i = 0; i < n_in; i++) {
        int s = in_sizes[i];
        if      (s == N_NODES * IN_DIM)  ix = i;
        else if (s == N_EDGES)           { if (isrc < 0) isrc = i; else idst = i; }
        else if (s == N_NODES)           ibatch = i;
        else if (s == IN_DIM * HID)      { if (iW1 < 0) iW1 = i; else iW2 = i; }
        else if (s == HID)               ib1 = i;
        else if (s == HID2)              ib2 = i;
        else if (s == HID2 * OUT_DIM)    iWfc = i;
        else if (s == OUT_DIM)           ibfc = i;
    }
    if (in_sizes[0] != N_NODES * IN_DIM) { int tmp = isrc; isrc = idst; idst = tmp; }

    const float* x     = (const float*)d_in[ix];
    const void*  src   = d_in[isrc];
    const void*  dst   = d_in[idst];
    const void*  batch = d_in[ibatch];
    const float* W1    = (const float*)d_in[iW1];
    const float* b1    = (const float*)d_in[ib1];
    const float* W2    = (const float*)d_in[iW2];
    const float* b2    = (const float*)d_in[ib2];
    const float* Wfc   = (const float*)d_in[iWfc];
    const float* bfc   = (const float*)d_in[ibfc];
    float* out = (float*)d_out;

    const int TPB = 256;
    const int nodeBlocks = (N_NODES + TPB - 1) / TPB;
    const int edgeBlocks = (N_EDGES + TPB - 1) / TPB;
    const int nvecBlocks = (N_NODES * 32 + TPB - 1) / TPB;   // node*32 threads

    k_detect<<<1, 32>>>((const int*)src);

    // CSR build (shared by both layers): hist -> scan(+dinv) -> fill
    k_zero_csr<<<nodeBlocks, TPB>>>();
    k_hist    <<<edgeBlocks, TPB>>>(dst);
    k_scan    <<<1, 1024>>>();
    k_fill    <<<edgeBlocks, TPB>>>(src, dst);

    // layer 1: gather-aggregate x (128-dim), then GEMM (+bias,relu)
    k_gather1<<<nvecBlocks, TPB>>>((const float4*)x);
    {
        dim3 grid(HID / 128, (N_NODES + 127) / 128);
        k_gemm1<<<grid, 256>>>(W1, b1);
    }

    // layer 2: GEMM first (output 128-dim), then gather-aggregate
    {
        dim3 grid(HID2 / 128, (N_NODES + 127) / 128);
        k_gemm2<<<grid, 256>>>(W2);
    }
    k_gather2<<<nvecBlocks, TPB>>>();

    // pool + fc
    k_zero_pool<<<(N_GRAPHS * HID2 + TPB - 1) / TPB, TPB>>>();
    k_pool     <<<nvecBlocks, TPB>>>(batch, b2);
    k_out      <<<1, N_GRAPHS * OUT_DIM>>>(Wfc, bfc, out);
}

// round 11
// speedup vs baseline: 1.3497x; 1.3497x over previous
#include <cuda_runtime.h>

// ---------------- problem constants ----------------
#define N_NODES  50000
#define N_EDGES  640000
#define N_GRAPHS 64
#define IN_DIM   128
#define HID      256
#define HID2     128   // HID/2
#define OUT_DIM  4

#define SCAN_TPB   256
#define SCAN_BLKS  ((N_NODES + SCAN_TPB - 1) / SCAN_TPB)   // 196

// ---------------- scratch (static device arrays; no allocation) ----------------
// RULE: these symbols are ONLY referenced inside device code; never passed as
// kernel arguments from host (host shadow address + ATS = silent wrong buffer).
__device__ float  g_dinv[N_NODES];                 // rsqrt(deg+1)
__device__ int    g_count [N_NODES];               // in-degree histogram
__device__ int    g_cursor[N_NODES];               // CSR fill cursors
__device__ int    g_rowptr[N_NODES + 1];           // CSR row pointers (by dst)
__device__ int    g_bsum [SCAN_BLKS];               // per-block sums
__device__ int    g_boff [SCAN_BLKS];               // per-block exclusive offsets
__device__ int    g_esrc [N_EDGES];                // CSR: src node per slot
__device__ float  g_enorm[N_EDGES];                // CSR: dinv[s]*dinv[d] per slot
__device__ float4 g_agg1[N_NODES * (IN_DIM / 4)];  // aggregated x      [N,128]
__device__ float  g_h1 [N_NODES * HID];            // relu(agg1@W1+b1)  [N,256]
__device__ float4 g_m2  [N_NODES * (HID2 / 4)];    // h1@W2             [N,128]
__device__ float4 g_agg2[N_NODES * (HID2 / 4)];    // aggregated m2     [N,128]
__device__ float  g_pool[N_GRAPHS * HID2];         // per-graph sums
__device__ float  g_cnt [N_GRAPHS];                // per-graph counts
__device__ int    g_idx64;                         // 1 if index arrays are int64

// ---------------- helpers ----------------
__device__ __forceinline__ void red_add_v4(float* addr, float4 v) {
    asm volatile("red.global.add.v4.f32 [%0], {%1,%2,%3,%4};"
                 :: "l"(addr), "f"(v.x), "f"(v.y), "f"(v.z), "f"(v.w)
                 : "memory");
}

__device__ __forceinline__ int get_idx(const void* p, int i, int is64) {
    long long v;
    if (is64) v = __ldg(((const long long*)p) + i);
    else      v = __ldg(((const int*)p) + i);
    return (int)v;
}

__device__ __forceinline__ unsigned f2tf32(float f) {
    unsigned r;
    asm("cvt.rna.tf32.f32 %0, %1;" : "=r"(r) : "f"(f));
    return r;
}

// m16n8k8 tf32 MMA, fp32 accumulate (D += A*B), row.col
__device__ __forceinline__ void mma_tf32(float* d, const unsigned* a, const unsigned* b) {
    asm volatile(
        "mma.sync.aligned.m16n8k8.row.col.f32.tf32.tf32.f32 "
        "{%0,%1,%2,%3}, {%4,%5,%6,%7}, {%8,%9}, {%0,%1,%2,%3};"
        : "+f"(d[0]), "+f"(d[1]), "+f"(d[2]), "+f"(d[3])
        : "r"(a[0]), "r"(a[1]), "r"(a[2]), "r"(a[3]), "r"(b[0]), "r"(b[1]));
}

// ---------------- index dtype detection ----------------
__global__ void k_detect(const int* p) {
    int lane = threadIdx.x;
    int nz = 0;
    for (int i = lane; i < 4096; i += 32)
        if (p[2 * i + 1] != 0) nz = 1;
    unsigned m = __ballot_sync(0xffffffffu, nz);
    if (lane == 0) g_idx64 = (m == 0u) ? 1 : 0;
}

// ---------------- CSR build ----------------
__global__ void k_zero_csr() {
    int i = blockIdx.x * blockDim.x + threadIdx.x;
    if (i < N_NODES) g_count[i] = 0;
}

__global__ void k_hist(const void* __restrict__ dst) {
    int e = blockIdx.x * blockDim.x + threadIdx.x;
    if (e < N_EDGES) {
        int d = get_idx(dst, e, g_idx64);
        if ((unsigned)d < (unsigned)N_NODES) atomicAdd(&g_count[d], 1);
    }
}

// ---- two-level parallel scan (replaces the 103us single-block scan) ----
// 1) per-block sums
__global__ void __launch_bounds__(SCAN_TPB) k_blocksum() {
    __shared__ int sh[SCAN_TPB / 32];
    int i = blockIdx.x * SCAN_TPB + threadIdx.x;
    int v = (i < N_NODES) ? g_count[i] : 0;
    #pragma unroll
    for (int o = 16; o > 0; o >>= 1) v += __shfl_down_sync(0xffffffffu, v, o);
    if ((threadIdx.x & 31) == 0) sh[threadIdx.x >> 5] = v;
    __syncthreads();
    if (threadIdx.x < SCAN_TPB / 32) {
        int s = sh[threadIdx.x];
        #pragma unroll
        for (int o = SCAN_TPB / 64; o > 0; o >>= 1)
            s += __shfl_down_sync(0xffffffffu, s, o);
        if (threadIdx.x == 0) g_bsum[blockIdx.x] = s;
    }
}

// 2) scan the 196 block sums (single small block)
__global__ void __launch_bounds__(256) k_scanpart() {
    __shared__ int sh[256];
    int t = threadIdx.x;
    int v = (t < SCAN_BLKS) ? g_bsum[t] : 0;
    sh[t] = v;
    __syncthreads();
    for (int d = 1; d < 256; d <<= 1) {
        int u = (t >= d) ? sh[t - d] : 0;
        __syncthreads();
        sh[t] += u;
        __syncthreads();
    }
    if (t < SCAN_BLKS) g_boff[t] = sh[t] - v;      // exclusive
    if (t == 0) g_rowptr[N_NODES] = N_EDGES;
}

// 3) per-block exclusive scan + offset -> rowptr; also dinv + cursor
__global__ void __launch_bounds__(SCAN_TPB) k_rowptr() {
    __shared__ int sh[SCAN_TPB];
    int t = threadIdx.x;
    int i = blockIdx.x * SCAN_TPB + t;
    int c = (i < N_NODES) ? g_count[i] : 0;
    sh[t] = c;
    __syncthreads();
    for (int d = 1; d < SCAN_TPB; d <<= 1) {
        int u = (t >= d) ? sh[t - d] : 0;
        __syncthreads();
        sh[t] += u;
        __syncthreads();
    }
    if (i < N_NODES) {
        g_rowptr[i] = g_boff[blockIdx.x] + sh[t] - c;   // exclusive
        g_dinv[i]   = rsqrtf((float)c + 1.0f);
        g_cursor[i] = 0;
    }
}

__global__ void k_fill(const void* __restrict__ src, const void* __restrict__ dst) {
    int e = blockIdx.x * blockDim.x + threadIdx.x;
    if (e >= N_EDGES) return;
    int is64 = g_idx64;
    int s = get_idx(src, e, is64);
    int d = get_idx(dst, e, is64);
    if ((unsigned)s >= (unsigned)N_NODES || (unsigned)d >= (unsigned)N_NODES) return;
    int pos = g_rowptr[d] + atomicAdd(&g_cursor[d], 1);
    g_esrc [pos] = s;
    g_enorm[pos] = g_dinv[s] * g_dinv[d];
}

// ---------------- CSR gather aggregation ----------------
// One warp per destination node; lane j owns float4 column j.
__device__ __forceinline__ void gather_body(const float4* __restrict__ feat,
                                            float4* __restrict__ agg) {
    int wid = (blockIdx.x * blockDim.x + threadIdx.x) >> 5;
    if (wid >= N_NODES) return;
    int j = threadIdx.x & 31;
    float di = g_dinv[wid];
    float4 v0 = feat[(size_t)wid * 32 + j];
    float s2 = di * di;
    float4 acc = make_float4(v0.x * s2, v0.y * s2, v0.z * s2, v0.w * s2);

    int i   = g_rowptr[wid];
    int end = g_rowptr[wid + 1];
    for (; i + 1 < end; i += 2) {
        int   s0 = __ldg(&g_esrc[i]),      s1 = __ldg(&g_esrc[i + 1]);
        float w0 = __ldg(&g_enorm[i]),     w1 = __ldg(&g_enorm[i + 1]);
        float4 a = feat[(size_t)s0 * 32 + j];
        float4 b = feat[(size_t)s1 * 32 + j];
        acc.x += w0 * a.x + w1 * b.x;
        acc.y += w0 * a.y + w1 * b.y;
        acc.z += w0 * a.z + w1 * b.z;
        acc.w += w0 * a.w + w1 * b.w;
    }
    if (i < end) {
        int   s0 = __ldg(&g_esrc[i]);
        float w0 = __ldg(&g_enorm[i]);
        float4 a = feat[(size_t)s0 * 32 + j];
        acc.x += w0 * a.x; acc.y += w0 * a.y;
        acc.z += w0 * a.z; acc.w += w0 * a.w;
    }
    agg[(size_t)wid * 32 + j] = acc;
}

__global__ void k_gather1(const float4* __restrict__ x) { gather_body(x, g_agg1); }
__global__ void k_gather2()                             { gather_body(g_m2, g_agg2); }

// ---------------- GEMM via mma.sync m16n8k8 tf32 (fp32 accumulate) ----------------
template <int KDIM, int NDIM, bool RELU_BIAS>
__device__ __forceinline__ void gemm_mma_body(const float* __restrict__ A,
                                              const float* __restrict__ B,
                                              const float* __restrict__ bias,
                                              float* __restrict__ C) {
    constexpr int BM = 128, BN = 128, BK = 32;
    constexpr int ASTR = 36;
    constexpr int BSTR = 136;
    __shared__ unsigned As[BM * ASTR];
    __shared__ unsigned Bs[BK * BSTR];

    const int t    = threadIdx.x;
    const int lane = t & 31;
    const int w    = t >> 5;
    const int mw   = w & 3;
    const int nw   = w >> 2;
    const int g    = lane >> 2;
    const int tg   = lane & 3;
    const int cRow = blockIdx.y * BM;
    const int cCol = blockIdx.x * BN;

    float acc[2][8][4];
    #pragma unroll
    for (int mt = 0; mt < 2; mt++)
        #pragma unroll
        for (int nt = 0; nt < 8; nt++)
            #pragma unroll
            for (int i = 0; i < 4; i++) acc[mt][nt][i] = 0.0f;

    for (int k0 = 0; k0 < KDIM; k0 += BK) {
        #pragma unroll
        for (int i = 0; i < 4; i++) {
            int f   = t + 256 * i;
            int row = f >> 3;
            int c4  = f & 7;
            float4 v = make_float4(0.f, 0.f, 0.f, 0.f);
            if (cRow + row < N_NODES)
                v = *(const float4*)(A + (size_t)(cRow + row) * KDIM + k0 + c4 * 4);
            uint4 u = make_uint4(f2tf32(v.x), f2tf32(v.y), f2tf32(v.z), f2tf32(v.w));
            *(uint4*)&As[row * ASTR + c4 * 4] = u;
        }
        #pragma unroll
        for (int i = 0; i < 4; i++) {
            int f   = t + 256 * i;
            int row = f >> 5;
            int c4  = f & 31;
            float4 v = *(const float4*)(B + (size_t)(k0 + row) * NDIM + cCol + c4 * 4);
            uint4 u = make_uint4(f2tf32(v.x), f2tf32(v.y), f2tf32(v.z), f2tf32(v.w));
            *(uint4*)&Bs[row * BSTR + c4 * 4] = u;
        }
        __syncthreads();

        #pragma unroll
        for (int kk = 0; kk < BK; kk += 8) {
            unsigned a[2][4];
            #pragma unroll
            for (int mt = 0; mt < 2; mt++) {
                int r0 = mw * 32 + mt * 16 + g;
                a[mt][0] = As[r0 * ASTR + kk + tg];
                a[mt][1] = As[(r0 + 8) * ASTR + kk + tg];
                a[mt][2] = As[r0 * ASTR + kk + tg + 4];
                a[mt][3] = As[(r0 + 8) * ASTR + kk + tg + 4];
            }
            #pragma unroll
            for (int nt = 0; nt < 8; nt++) {
                unsigned b[2];
                int c0 = nw * 64 + nt * 8 + g;
                b[0] = Bs[(kk + tg)     * BSTR + c0];
                b[1] = Bs[(kk + tg + 4) * BSTR + c0];
                mma_tf32(acc[0][nt], a[0], b);
                mma_tf32(acc[1][nt], a[1], b);
            }
        }
        __syncthreads();
    }

    #pragma unroll
    for (int mt = 0; mt < 2; mt++) {
        int rBase = cRow + mw * 32 + mt * 16 + g;
        #pragma unroll
        for (int nt = 0; nt < 8; nt++) {
            int c = cCol + nw * 64 + nt * 8 + 2 * tg;
            float2 lo = make_float2(acc[mt][nt][0], acc[mt][nt][1]);
            float2 hi = make_float2(acc[mt][nt][2], acc[mt][nt][3]);
            if (RELU_BIAS) {
                float2 bb = *(const float2*)(bias + c);
                lo.x = fmaxf(lo.x + bb.x, 0.f); lo.y = fmaxf(lo.y + bb.y, 0.f);
                hi.x = fmaxf(hi.x + bb.x, 0.f); hi.y = fmaxf(hi.y + bb.y, 0.f);
            }
            if (rBase < N_NODES)
                *(float2*)(C + (size_t)rBase * NDIM + c) = lo;
            if (rBase + 8 < N_NODES)
                *(float2*)(C + (size_t)(rBase + 8) * NDIM + c) = hi;
        }
    }
}

__global__ void __launch_bounds__(256) k_gemm1(const float* __restrict__ W1,
                                               const float* __restrict__ b1) {
    gemm_mma_body<IN_DIM, HID, true>((const float*)g_agg1, W1, b1, g_h1);
}

__global__ void __launch_bounds__(256) k_gemm2(const float* __restrict__ W2) {
    gemm_mma_body<HID, HID2, false>(g_h1, W2, nullptr, (float*)g_m2);
}

// ---------------- pooling ----------------
__global__ void k_zero_pool() {
    int i = blockIdx.x * blockDim.x + threadIdx.x;
    if (i < N_GRAPHS * HID2) g_pool[i] = 0.0f;
    if (i < N_GRAPHS) g_cnt[i] = 0.0f;
}

__global__ void k_pool(const void* __restrict__ batch, const float* __restrict__ b2) {
    int t = blockIdx.x * blockDim.x + threadIdx.x;
    if (t >= N_NODES * 32) return;
    int node = t >> 5;
    int j    = t & 31;
    int b    = get_idx(batch, node, g_idx64);
    if ((unsigned)b >= (unsigned)N_GRAPHS) return;
    float4 v  = g_agg2[t];
    float4 bb = ((const float4*)b2)[j];
    v.x = fmaxf(v.x + bb.x, 0.f);
    v.y = fmaxf(v.y + bb.y, 0.f);
    v.z = fmaxf(v.z + bb.z, 0.f);
    v.w = fmaxf(v.w + bb.w, 0.f);
    red_add_v4(&g_pool[b * HID2 + j * 4], v);
    if (j == 0) atomicAdd(&g_cnt[b], 1.0f);
}

__global__ void k_out(const float* __restrict__ Wfc, const float* __restrict__ bfc,
                      float* __restrict__ out) {
    int t = threadIdx.x;
    if (t >= N_GRAPHS * OUT_DIM) return;
    int g = t >> 2;
    int o = t & 3;
    float inv = 1.0f / fmaxf(g_cnt[g], 1.0f);
    float s = 0.0f;
    #pragma unroll 16
    for (int k = 0; k < HID2; k++)
        s = fmaf(g_pool[g * HID2 + k], Wfc[k * OUT_DIM + o], s);
    out[t] = s * inv + bfc[o];
}

// ---------------- launch ----------------
extern "C" void kernel_launch(void* const* d_in, const int* in_sizes, int n_in,
                              void* d_out, int out_size) {
    int ix = -1, isrc = -1, idst = -1, ibatch = -1, iW1 = -1, iW2 = -1;
    int ib1 = -1, ib2 = -1, iWfc = -1, ibfc = -1;
    for (int i = 0; i < n_in; i++) {
        int s = in_sizes[i];
        if      (s == N_NODES * IN_DIM)  ix = i;
        else if (s == N_EDGES)           { if (isrc < 0) isrc = i; else idst = i; }
        else if (s == N_NODES)           ibatch = i;
        else if (s == IN_DIM * HID)      { if (iW1 < 0) iW1 = i; else iW2 = i; }
        else if (s == HID)               ib1 = i;
        else if (s == HID2)              ib2 = i;
        else if (s == HID2 * OUT_DIM)    iWfc = i;
        else if (s == OUT_DIM)           ibfc = i;
    }
    if (in_sizes[0] != N_NODES * IN_DIM) { int tmp = isrc; isrc = idst; idst = tmp; }

    const float* x     = (const float*)d_in[ix];
    const void*  src   = d_in[isrc];
    const void*  dst   = d_in[idst];
    const void*  batch = d_in[ibatch];
    const float* W1    = (const float*)d_in[iW1];
    const float* b1    = (const float*)d_in[ib1];
    const float* W2    = (const float*)d_in[iW2];
    const float* b2    = (const float*)d_in[ib2];
    const float* Wfc   = (const float*)d_in[iWfc];
    const float* bfc   = (const float*)d_in[ibfc];
    float* out = (float*)d_out;

    const int TPB = 256;
    const int nodeBlocks = (N_NODES + TPB - 1) / TPB;
    const int edgeBlocks = (N_EDGES + TPB - 1) / TPB;
    const int nvecBlocks = (N_NODES * 32 + TPB - 1) / TPB;   // node*32 threads

    k_detect<<<1, 32>>>((const int*)src);

    // CSR build: hist -> two-level scan -> fill
    k_zero_csr<<<nodeBlocks, TPB>>>();
    k_hist    <<<edgeBlocks, TPB>>>(dst);
    k_blocksum<<<SCAN_BLKS, SCAN_TPB>>>();
    k_scanpart<<<1, 256>>>();
    k_rowptr  <<<SCAN_BLKS, SCAN_TPB>>>();
    k_fill    <<<edgeBlocks, TPB>>>(src, dst);

    // layer 1: gather-aggregate x (128-dim), then GEMM (+bias,relu)
    k_gather1<<<nvecBlocks, TPB>>>((const float4*)x);
    {
        dim3 grid(HID / 128, (N_NODES + 127) / 128);
        k_gemm1<<<grid, 256>>>(W1, b1);
    }

    // layer 2: GEMM first (output 128-dim), then gather-aggregate
    {
        dim3 grid(HID2 / 128, (N_NODES + 127) / 128);
        k_gemm2<<<grid, 256>>>(W2);
    }
    k_gather2<<<nvecBlocks, TPB>>>();

    // pool + fc
    k_zero_pool<<<(N_GRAPHS * HID2 + TPB - 1) / TPB, TPB>>>();
    k_pool     <<<nvecBlocks, TPB>>>(batch, b2);
    k_out      <<<1, N_GRAPHS * OUT_DIM>>>(Wfc, bfc, out);
}

// round 12
// speedup vs baseline: 1.6214x; 1.2013x over previous
#include <cuda_runtime.h>

// ---------------- problem constants ----------------
#define N_NODES  50000
#define N_EDGES  640000
#define N_GRAPHS 64
#define IN_DIM   128
#define HID      256
#define HID2     128   // HID/2
#define OUT_DIM  4

#define SCAN_TPB   256
#define SCAN_BLKS  ((N_NODES + SCAN_TPB - 1) / SCAN_TPB)   // 196

// ---------------- scratch (static device arrays; no allocation) ----------------
// RULE: symbols referenced ONLY inside device code (host shadow + ATS trap).
__device__ float    g_dinv[N_NODES];                  // rsqrt(deg+1)
__device__ int      g_count [N_NODES];
__device__ int      g_cursor[N_NODES];
__device__ int      g_rowptr[N_NODES + 1];
__device__ int      g_bsum [SCAN_BLKS];
__device__ int      g_boff [SCAN_BLKS];
__device__ int      g_esrc [N_EDGES];
__device__ float    g_enorm[N_EDGES];
__device__ unsigned g_w1t[IN_DIM * HID];              // W1 as tf32 bits
__device__ unsigned g_w2t[HID * HID2];                // W2 as tf32 bits
__device__ uint4    g_agg1[N_NODES * (IN_DIM / 4)];   // aggregated x (tf32 bits)
__device__ unsigned g_h1 [N_NODES * HID];             // relu(agg1@W1+b1) (tf32 bits)
__device__ float4   g_m2  [N_NODES * (HID2 / 4)];     // h1@W2  [N,128] fp32
__device__ float    g_pool[N_GRAPHS * HID2];
__device__ float    g_cnt [N_GRAPHS];
__device__ int      g_idx64;

// ---------------- helpers ----------------
__device__ __forceinline__ void red_add_v4(float* addr, float4 v) {
    asm volatile("red.global.add.v4.f32 [%0], {%1,%2,%3,%4};"
                 :: "l"(addr), "f"(v.x), "f"(v.y), "f"(v.z), "f"(v.w)
                 : "memory");
}

__device__ __forceinline__ int get_idx(const void* p, int i, int is64) {
    long long v;
    if (is64) v = __ldg(((const long long*)p) + i);
    else      v = __ldg(((const int*)p) + i);
    return (int)v;
}

__device__ __forceinline__ unsigned f2tf32(float f) {
    unsigned r;
    asm("cvt.rna.tf32.f32 %0, %1;" : "=r"(r) : "f"(f));
    return r;
}

__device__ __forceinline__ void mma_tf32(float* d, const unsigned* a, const unsigned* b) {
    asm volatile(
        "mma.sync.aligned.m16n8k8.row.col.f32.tf32.tf32.f32 "
        "{%0,%1,%2,%3}, {%4,%5,%6,%7}, {%8,%9}, {%0,%1,%2,%3};"
        : "+f"(d[0]), "+f"(d[1]), "+f"(d[2]), "+f"(d[3])
        : "r"(a[0]), "r"(a[1]), "r"(a[2]), "r"(a[3]), "r"(b[0]), "r"(b[1]));
}

__device__ __forceinline__ void cp_async16(void* smem, const void* gmem, int szbytes) {
    unsigned saddr = (unsigned)__cvta_generic_to_shared(smem);
    asm volatile("cp.async.cg.shared.global [%0], [%1], 16, %2;"
                 :: "r"(saddr), "l"(gmem), "r"(szbytes));
}
__device__ __forceinline__ void cp_commit() {
    asm volatile("cp.async.commit_group;");
}
template <int N>
__device__ __forceinline__ void cp_wait() {
    asm volatile("cp.async.wait_group %0;" :: "n"(N));
}

// ---------------- index dtype detection ----------------
__global__ void k_detect(const int* p) {
    int lane = threadIdx.x;
    int nz = 0;
    for (int i = lane; i < 4096; i += 32)
        if (p[2 * i + 1] != 0) nz = 1;
    unsigned m = __ballot_sync(0xffffffffu, nz);
    if (lane == 0) g_idx64 = (m == 0u) ? 1 : 0;
}

// ---------------- weight pre-conversion to tf32 ----------------
__global__ void k_cvtw(const float* __restrict__ W1, const float* __restrict__ W2) {
    int i = blockIdx.x * blockDim.x + threadIdx.x;
    if (i < IN_DIM * HID) g_w1t[i] = f2tf32(W1[i]);
    if (i < HID * HID2)   g_w2t[i] = f2tf32(W2[i]);
}

// ---------------- CSR build ----------------
__global__ void k_zero_csr() {
    int i = blockIdx.x * blockDim.x + threadIdx.x;
    if (i < N_NODES) g_count[i] = 0;
}

__global__ void k_hist(const void* __restrict__ dst) {
    int e = blockIdx.x * blockDim.x + threadIdx.x;
    if (e < N_EDGES) {
        int d = get_idx(dst, e, g_idx64);
        if ((unsigned)d < (unsigned)N_NODES) atomicAdd(&g_count[d], 1);
    }
}

__global__ void __launch_bounds__(SCAN_TPB) k_blocksum() {
    __shared__ int sh[SCAN_TPB / 32];
    int i = blockIdx.x * SCAN_TPB + threadIdx.x;
    int v = (i < N_NODES) ? g_count[i] : 0;
    #pragma unroll
    for (int o = 16; o > 0; o >>= 1) v += __shfl_down_sync(0xffffffffu, v, o);
    if ((threadIdx.x & 31) == 0) sh[threadIdx.x >> 5] = v;
    __syncthreads();
    if (threadIdx.x < SCAN_TPB / 32) {
        int s = sh[threadIdx.x];
        #pragma unroll
        for (int o = SCAN_TPB / 64; o > 0; o >>= 1)
            s += __shfl_down_sync(0xffffffffu, s, o);
        if (threadIdx.x == 0) g_bsum[blockIdx.x] = s;
    }
}

__global__ void __launch_bounds__(256) k_scanpart() {
    __shared__ int sh[256];
    int t = threadIdx.x;
    int v = (t < SCAN_BLKS) ? g_bsum[t] : 0;
    sh[t] = v;
    __syncthreads();
    for (int d = 1; d < 256; d <<= 1) {
        int u = (t >= d) ? sh[t - d] : 0;
        __syncthreads();
        sh[t] += u;
        __syncthreads();
    }
    if (t < SCAN_BLKS) g_boff[t] = sh[t] - v;
    if (t == 0) g_rowptr[N_NODES] = N_EDGES;
}

__global__ void __launch_bounds__(SCAN_TPB) k_rowptr() {
    __shared__ int sh[SCAN_TPB];
    int t = threadIdx.x;
    int i = blockIdx.x * SCAN_TPB + t;
    int c = (i < N_NODES) ? g_count[i] : 0;
    sh[t] = c;
    __syncthreads();
    for (int d = 1; d < SCAN_TPB; d <<= 1) {
        int u = (t >= d) ? sh[t - d] : 0;
        __syncthreads();
        sh[t] += u;
        __syncthreads();
    }
    if (i < N_NODES) {
        g_rowptr[i] = g_boff[blockIdx.x] + sh[t] - c;
        g_dinv[i]   = rsqrtf((float)c + 1.0f);
        g_cursor[i] = 0;
    }
}

__global__ void k_fill(const void* __restrict__ src, const void* __restrict__ dst) {
    int e = blockIdx.x * blockDim.x + threadIdx.x;
    if (e >= N_EDGES) return;
    int is64 = g_idx64;
    int s = get_idx(src, e, is64);
    int d = get_idx(dst, e, is64);
    if ((unsigned)s >= (unsigned)N_NODES || (unsigned)d >= (unsigned)N_NODES) return;
    int pos = g_rowptr[d] + atomicAdd(&g_cursor[d], 1);
    g_esrc [pos] = s;
    g_enorm[pos] = g_dinv[s] * g_dinv[d];
}

// ---------------- gather 1: agg1 = tf32(self + neighbors) of x ----------------
__global__ void k_gather1(const float4* __restrict__ x) {
    int wid = (blockIdx.x * blockDim.x + threadIdx.x) >> 5;
    if (wid >= N_NODES) return;
    int j = threadIdx.x & 31;
    float di = g_dinv[wid];
    float4 v0 = x[(size_t)wid * 32 + j];
    float s2 = di * di;
    float4 acc = make_float4(v0.x * s2, v0.y * s2, v0.z * s2, v0.w * s2);

    int i   = g_rowptr[wid];
    int end = g_rowptr[wid + 1];
    for (; i + 1 < end; i += 2) {
        int   s0 = __ldg(&g_esrc[i]),  s1 = __ldg(&g_esrc[i + 1]);
        float w0 = __ldg(&g_enorm[i]), w1 = __ldg(&g_enorm[i + 1]);
        float4 a = x[(size_t)s0 * 32 + j];
        float4 b = x[(size_t)s1 * 32 + j];
        acc.x += w0 * a.x + w1 * b.x;
        acc.y += w0 * a.y + w1 * b.y;
        acc.z += w0 * a.z + w1 * b.z;
        acc.w += w0 * a.w + w1 * b.w;
    }
    if (i < end) {
        int   s0 = __ldg(&g_esrc[i]);
        float w0 = __ldg(&g_enorm[i]);
        float4 a = x[(size_t)s0 * 32 + j];
        acc.x += w0 * a.x; acc.y += w0 * a.y;
        acc.z += w0 * a.z; acc.w += w0 * a.w;
    }
    g_agg1[(size_t)wid * 32 + j] =
        make_uint4(f2tf32(acc.x), f2tf32(acc.y), f2tf32(acc.z), f2tf32(acc.w));
}

// ---------------- gather 2 + fused pooling ----------------
// pool[batch[d]] += relu(agg2[d] + b2); cnt[batch[d]] += 1
__global__ void k_gather2(const void* __restrict__ batch, const float* __restrict__ b2) {
    int wid = (blockIdx.x * blockDim.x + threadIdx.x) >> 5;
    if (wid >= N_NODES) return;
    int j = threadIdx.x & 31;
    float di = g_dinv[wid];
    float4 v0 = g_m2[(size_t)wid * 32 + j];
    float s2 = di * di;
    float4 acc = make_float4(v0.x * s2, v0.y * s2, v0.z * s2, v0.w * s2);

    int i   = g_rowptr[wid];
    int end = g_rowptr[wid + 1];
    for (; i + 1 < end; i += 2) {
        int   s0 = __ldg(&g_esrc[i]),  s1 = __ldg(&g_esrc[i + 1]);
        float w0 = __ldg(&g_enorm[i]), w1 = __ldg(&g_enorm[i + 1]);
        float4 a = g_m2[(size_t)s0 * 32 + j];
        float4 b = g_m2[(size_t)s1 * 32 + j];
        acc.x += w0 * a.x + w1 * b.x;
        acc.y += w0 * a.y + w1 * b.y;
        acc.z += w0 * a.z + w1 * b.z;
        acc.w += w0 * a.w + w1 * b.w;
    }
    if (i < end) {
        int   s0 = __ldg(&g_esrc[i]);
        float w0 = __ldg(&g_enorm[i]);
        float4 a = g_m2[(size_t)s0 * 32 + j];
        acc.x += w0 * a.x; acc.y += w0 * a.y;
        acc.z += w0 * a.z; acc.w += w0 * a.w;
    }

    int b = get_idx(batch, wid, g_idx64);
    if ((unsigned)b >= (unsigned)N_GRAPHS) return;
    float4 bb = ((const float4*)b2)[j];
    acc.x = fmaxf(acc.x + bb.x, 0.f);
    acc.y = fmaxf(acc.y + bb.y, 0.f);
    acc.z = fmaxf(acc.z + bb.z, 0.f);
    acc.w = fmaxf(acc.w + bb.w, 0.f);
    red_add_v4(&g_pool[b * HID2 + j * 4], acc);
    if (j == 0) atomicAdd(&g_cnt[b], 1.0f);
}

// ---------------- GEMM: cp.async double-buffered, operands pre-tf32 ----------------
// C[M,N] = A[M,K] @ B[K,N]. BM=128, BN=128, BK=16, 2-stage pipeline.
// 8 warps 4(m)x2(n); warp tile 32m x 64n. Shared: (128*20 + 16*136)*4*2 = 37,888 B.
// OUT_TF32: epilogue writes tf32 bits (for h1); else fp32.
template <int KDIM, int NDIM, bool RELU_BIAS, bool OUT_TF32>
__device__ __forceinline__ void gemm_pipe_body(const unsigned* __restrict__ A,
                                               const unsigned* __restrict__ B,
                                               const float* __restrict__ bias,
                                               void* __restrict__ Cout) {
    constexpr int BM = 128, BN = 128, BK = 16;
    constexpr int ASTR = 20;
    constexpr int BSTR = 136;
    constexpr int KT = KDIM / BK;
    __shared__ unsigned As[2][BM * ASTR];
    __shared__ unsigned Bs[2][BK * BSTR];

    const int t    = threadIdx.x;
    const int lane = t & 31;
    const int w    = t >> 5;
    const int mw   = w & 3;
    const int nw   = w >> 2;
    const int g    = lane >> 2;
    const int tg   = lane & 3;
    const int cRow = blockIdx.y * BM;
    const int cCol = blockIdx.x * BN;

    float acc[2][8][4];
    #pragma unroll
    for (int mt = 0; mt < 2; mt++)
        #pragma unroll
        for (int nt = 0; nt < 8; nt++)
            #pragma unroll
            for (int i = 0; i < 4; i++) acc[mt][nt][i] = 0.0f;

    // tile loader: 2 A-float4 + 2 B-float4 per thread
    auto load_tile = [&](int kt, int buf) {
        int k0 = kt * BK;
        #pragma unroll
        for (int i = 0; i < 2; i++) {
            int fa  = t + 256 * i;            // 0..511
            int ar  = fa >> 2;                 // row 0..127
            int ac4 = fa & 3;                  // col-quad 0..3
            int sz  = (cRow + ar < N_NODES) ? 16 : 0;
            cp_async16(&As[buf][ar * ASTR + ac4 * 4],
                       A + (size_t)(cRow + ar) * KDIM + k0 + ac4 * 4, sz);
            int br  = fa >> 5;                 // row 0..15
            int bc4 = fa & 31;                 // col-quad 0..31
            cp_async16(&Bs[buf][br * BSTR + bc4 * 4],
                       B + (size_t)(k0 + br) * NDIM + cCol + bc4 * 4, 16);
        }
        cp_commit();
    };

    load_tile(0, 0);
    for (int kt = 0; kt < KT; kt++) {
        if (kt + 1 < KT) { load_tile(kt + 1, (kt + 1) & 1); cp_wait<1>(); }
        else             { cp_wait<0>(); }
        __syncthreads();
        const unsigned* as = As[kt & 1];
        const unsigned* bs = Bs[kt & 1];
        #pragma unroll
        for (int kk = 0; kk < BK; kk += 8) {
            unsigned a[2][4];
            #pragma unroll
            for (int mt = 0; mt < 2; mt++) {
                int r0 = mw * 32 + mt * 16 + g;
                a[mt][0] = as[r0 * ASTR + kk + tg];
                a[mt][1] = as[(r0 + 8) * ASTR + kk + tg];
                a[mt][2] = as[r0 * ASTR + kk + tg + 4];
                a[mt][3] = as[(r0 + 8) * ASTR + kk + tg + 4];
            }
            #pragma unroll
            for (int nt = 0; nt < 8; nt++) {
                unsigned b[2];
                int c0 = nw * 64 + nt * 8 + g;
                b[0] = bs[(kk + tg)     * BSTR + c0];
                b[1] = bs[(kk + tg + 4) * BSTR + c0];
                mma_tf32(acc[0][nt], a[0], b);
                mma_tf32(acc[1][nt], a[1], b);
            }
        }
        __syncthreads();
    }

    #pragma unroll
    for (int mt = 0; mt < 2; mt++) {
        int rBase = cRow + mw * 32 + mt * 16 + g;
        #pragma unroll
        for (int nt = 0; nt < 8; nt++) {
            int c = cCol + nw * 64 + nt * 8 + 2 * tg;
            float f0 = acc[mt][nt][0], f1 = acc[mt][nt][1];
            float f2 = acc[mt][nt][2], f3 = acc[mt][nt][3];
            if (RELU_BIAS) {
                float2 bb = *(const float2*)(bias + c);
                f0 = fmaxf(f0 + bb.x, 0.f); f1 = fmaxf(f1 + bb.y, 0.f);
                f2 = fmaxf(f2 + bb.x, 0.f); f3 = fmaxf(f3 + bb.y, 0.f);
            }
            if (OUT_TF32) {
                unsigned* C = (unsigned*)Cout;
                if (rBase < N_NODES) {
                    uint2 u = make_uint2(f2tf32(f0), f2tf32(f1));
                    *(uint2*)(C + (size_t)rBase * NDIM + c) = u;
                }
                if (rBase + 8 < N_NODES) {
                    uint2 u = make_uint2(f2tf32(f2), f2tf32(f3));
                    *(uint2*)(C + (size_t)(rBase + 8) * NDIM + c) = u;
                }
            } else {
                float* C = (float*)Cout;
                if (rBase < N_NODES)
                    *(float2*)(C + (size_t)rBase * NDIM + c) = make_float2(f0, f1);
                if (rBase + 8 < N_NODES)
                    *(float2*)(C + (size_t)(rBase + 8) * NDIM + c) = make_float2(f2, f3);
            }
        }
    }
}

__global__ void __launch_bounds__(256) k_gemm1(const float* __restrict__ b1) {
    gemm_pipe_body<IN_DIM, HID, true, true>((const unsigned*)g_agg1, g_w1t, b1, g_h1);
}

__global__ void __launch_bounds__(256) k_gemm2() {
    gemm_pipe_body<HID, HID2, false, false>(g_h1, g_w2t, nullptr, (float*)g_m2);
}

// ---------------- pooling tail ----------------
__global__ void k_zero_pool() {
    int i = blockIdx.x * blockDim.x + threadIdx.x;
    if (i < N_GRAPHS * HID2) g_pool[i] = 0.0f;
    if (i < N_GRAPHS) g_cnt[i] = 0.0f;
}

__global__ void k_out(const float* __restrict__ Wfc, const float* __restrict__ bfc,
                      float* __restrict__ out) {
    int t = threadIdx.x;
    if (t >= N_GRAPHS * OUT_DIM) return;
    int g = t >> 2;
    int o = t & 3;
    float inv = 1.0f / fmaxf(g_cnt[g], 1.0f);
    float s = 0.0f;
    #pragma unroll 16
    for (int k = 0; k < HID2; k++)
        s = fmaf(g_pool[g * HID2 + k], Wfc[k * OUT_DIM + o], s);
    out[t] = s * inv + bfc[o];
}

// ---------------- launch ----------------
extern "C" void kernel_launch(void* const* d_in, const int* in_sizes, int n_in,
                              void* d_out, int out_size) {
    int ix = -1, isrc = -1, idst = -1, ibatch = -1, iW1 = -1, iW2 = -1;
    int ib1 = -1, ib2 = -1, iWfc = -1, ibfc = -1;
    for (int i = 0; i < n_in; i++) {
        int s = in_sizes[i];
        if      (s == N_NODES * IN_DIM)  ix = i;
        else if (s == N_EDGES)           { if (isrc < 0) isrc = i; else idst = i; }
        else if (s == N_NODES)           ibatch = i;
        else if (s == IN_DIM * HID)      { if (iW1 < 0) iW1 = i; else iW2 = i; }
        else if (s == HID)               ib1 = i;
        else if (s == HID2)              ib2 = i;
        else if (s == HID2 * OUT_DIM)    iWfc = i;
        else if (s == OUT_DIM)           ibfc = i;
    }
    if (in_sizes[0] != N_NODES * IN_DIM) { int tmp = isrc; isrc = idst; idst = tmp; }

    const float* x     = (const float*)d_in[ix];
    const void*  src   = d_in[isrc];
    const void*  dst   = d_in[idst];
    const void*  batch = d_in[ibatch];
    const float* W1    = (const float*)d_in[iW1];
    const float* b1    = (const float*)d_in[ib1];
    const float* W2    = (const float*)d_in[iW2];
    const float* b2    = (const float*)d_in[ib2];
    const float* Wfc   = (const float*)d_in[iWfc];
    const float* bfc   = (const float*)d_in[ibfc];
    float* out = (float*)d_out;

    const int TPB = 256;
    const int nodeBlocks = (N_NODES + TPB - 1) / TPB;
    const int edgeBlocks = (N_EDGES + TPB - 1) / TPB;
    const int nvecBlocks = (N_NODES * 32 + TPB - 1) / TPB;

    k_detect<<<1, 32>>>((const int*)src);
    k_cvtw  <<<(IN_DIM * HID + TPB - 1) / TPB, TPB>>>(W1, W2);

    // CSR build
    k_zero_csr<<<nodeBlocks, TPB>>>();
    k_hist    <<<edgeBlocks, TPB>>>(dst);
    k_blocksum<<<SCAN_BLKS, SCAN_TPB>>>();
    k_scanpart<<<1, 256>>>();
    k_rowptr  <<<SCAN_BLKS, SCAN_TPB>>>();
    k_fill    <<<edgeBlocks, TPB>>>(src, dst);

    // layer 1
    k_gather1<<<nvecBlocks, TPB>>>((const float4*)x);
    {
        dim3 grid(HID / 128, (N_NODES + 127) / 128);
        k_gemm1<<<grid, 256>>>(b1);
    }

    // layer 2 (+fused pool)
    {
        dim3 grid(HID2 / 128, (N_NODES + 127) / 128);
        k_gemm2<<<grid, 256>>>();
    }
    k_zero_pool<<<(N_GRAPHS * HID2 + TPB - 1) / TPB, TPB>>>();
    k_gather2<<<nvecBlocks, TPB>>>(batch, b2);

    // fc
    k_out<<<1, N_GRAPHS * OUT_DIM>>>(Wfc, bfc, out);
}

// round 13
// speedup vs baseline: 1.6251x; 1.0023x over previous
#include <cuda_runtime.h>

// ---------------- problem constants ----------------
#define N_NODES  50000
#define N_EDGES  640000
#define N_GRAPHS 64
#define IN_DIM   128
#define HID      256
#define HID2     128   // HID/2
#define OUT_DIM  4

#define SCAN_TPB   256
#define SCAN_BLKS  ((N_NODES + SCAN_TPB - 1) / SCAN_TPB)   // 196

// ---------------- scratch (static device arrays; no allocation) ----------------
// RULE: symbols referenced ONLY inside device code (host shadow + ATS trap).
__device__ float    g_dinv[N_NODES];                  // rsqrt(deg+1)
__device__ int      g_count [N_NODES];
__device__ int      g_rowptr[N_NODES + 1];
__device__ int      g_bsum [SCAN_BLKS];
__device__ int      g_boff [SCAN_BLKS];
__device__ int      g_esrc [N_EDGES];
__device__ int      g_eoff [N_EDGES];                 // bucket-local offset per edge
__device__ float    g_enorm[N_EDGES];
__device__ unsigned g_w1t[IN_DIM * HID];              // W1 as tf32 bits
__device__ unsigned g_w2t[HID * HID2];                // W2 as tf32 bits
__device__ uint4    g_agg1[N_NODES * (IN_DIM / 4)];   // aggregated x (tf32 bits)
__device__ unsigned g_h1 [N_NODES * HID];             // relu(agg1@W1+b1) (tf32 bits)
__device__ float4   g_m2  [N_NODES * (HID2 / 4)];     // h1@W2  [N,128] fp32
__device__ float    g_pool[N_GRAPHS * HID2];
__device__ float    g_cnt [N_GRAPHS];
__device__ int      g_idx64;

// ---------------- helpers ----------------
__device__ __forceinline__ void red_add_v4(float* addr, float4 v) {
    asm volatile("red.global.add.v4.f32 [%0], {%1,%2,%3,%4};"
                 :: "l"(addr), "f"(v.x), "f"(v.y), "f"(v.z), "f"(v.w)
                 : "memory");
}

__device__ __forceinline__ int get_idx(const void* p, int i, int is64) {
    long long v;
    if (is64) v = __ldg(((const long long*)p) + i);
    else      v = __ldg(((const int*)p) + i);
    return (int)v;
}

__device__ __forceinline__ unsigned f2tf32(float f) {
    unsigned r;
    asm("cvt.rna.tf32.f32 %0, %1;" : "=r"(r) : "f"(f));
    return r;
}

__device__ __forceinline__ void mma_tf32(float* d, const unsigned* a, const unsigned* b) {
    asm volatile(
        "mma.sync.aligned.m16n8k8.row.col.f32.tf32.tf32.f32 "
        "{%0,%1,%2,%3}, {%4,%5,%6,%7}, {%8,%9}, {%0,%1,%2,%3};"
        : "+f"(d[0]), "+f"(d[1]), "+f"(d[2]), "+f"(d[3])
        : "r"(a[0]), "r"(a[1]), "r"(a[2]), "r"(a[3]), "r"(b[0]), "r"(b[1]));
}

__device__ __forceinline__ void cp_async16(void* smem, const void* gmem, int szbytes) {
    unsigned saddr = (unsigned)__cvta_generic_to_shared(smem);
    asm volatile("cp.async.cg.shared.global [%0], [%1], 16, %2;"
                 :: "r"(saddr), "l"(gmem), "r"(szbytes));
}
__device__ __forceinline__ void cp_commit() {
    asm volatile("cp.async.commit_group;");
}
template <int N>
__device__ __forceinline__ void cp_wait() {
    asm volatile("cp.async.wait_group %0;" :: "n"(N));
}

// ---------------- fused setup: detect dtype, cvt weights, zero count/pool ----
__global__ void k_setup(const int* __restrict__ srcprobe,
                        const float* __restrict__ W1, const float* __restrict__ W2) {
    int i = blockIdx.x * blockDim.x + threadIdx.x;
    if (i < N_NODES) g_count[i] = 0;
    if (i < N_GRAPHS * HID2) g_pool[i] = 0.0f;
    if (i < N_GRAPHS) g_cnt[i] = 0.0f;
    if (i < IN_DIM * HID) g_w1t[i] = f2tf32(W1[i]);
    if (i < HID * HID2)   g_w2t[i] = f2tf32(W2[i]);
    if (blockIdx.x == 0 && threadIdx.x < 32) {
        int lane = threadIdx.x;
        int nz = 0;
        for (int k = lane; k < 4096; k += 32)
            if (srcprobe[2 * k + 1] != 0) nz = 1;
        unsigned m = __ballot_sync(0xffffffffu, nz);
        if (lane == 0) g_idx64 = (m == 0u) ? 1 : 0;
    }
}

// ---------------- CSR build ----------------
// hist also records the bucket-local offset (single-pass fill trick)
__global__ void k_hist(const void* __restrict__ dst) {
    int e = blockIdx.x * blockDim.x + threadIdx.x;
    if (e < N_EDGES) {
        int d = get_idx(dst, e, g_idx64);
        if ((unsigned)d < (unsigned)N_NODES)
            g_eoff[e] = atomicAdd(&g_count[d], 1);
    }
}

__global__ void __launch_bounds__(SCAN_TPB) k_blocksum() {
    __shared__ int sh[SCAN_TPB / 32];
    int i = blockIdx.x * SCAN_TPB + threadIdx.x;
    int v = (i < N_NODES) ? g_count[i] : 0;
    #pragma unroll
    for (int o = 16; o > 0; o >>= 1) v += __shfl_down_sync(0xffffffffu, v, o);
    if ((threadIdx.x & 31) == 0) sh[threadIdx.x >> 5] = v;
    __syncthreads();
    if (threadIdx.x < SCAN_TPB / 32) {
        int s = sh[threadIdx.x];
        #pragma unroll
        for (int o = SCAN_TPB / 64; o > 0; o >>= 1)
            s += __shfl_down_sync(0xffffffffu, s, o);
        if (threadIdx.x == 0) g_bsum[blockIdx.x] = s;
    }
}

__global__ void __launch_bounds__(256) k_scanpart() {
    __shared__ int sh[256];
    int t = threadIdx.x;
    int v = (t < SCAN_BLKS) ? g_bsum[t] : 0;
    sh[t] = v;
    __syncthreads();
    for (int d = 1; d < 256; d <<= 1) {
        int u = (t >= d) ? sh[t - d] : 0;
        __syncthreads();
        sh[t] += u;
        __syncthreads();
    }
    if (t < SCAN_BLKS) g_boff[t] = sh[t] - v;
    if (t == 0) g_rowptr[N_NODES] = N_EDGES;
}

__global__ void __launch_bounds__(SCAN_TPB) k_rowptr() {
    __shared__ int sh[SCAN_TPB];
    int t = threadIdx.x;
    int i = blockIdx.x * SCAN_TPB + t;
    int c = (i < N_NODES) ? g_count[i] : 0;
    sh[t] = c;
    __syncthreads();
    for (int d = 1; d < SCAN_TPB; d <<= 1) {
        int u = (t >= d) ? sh[t - d] : 0;
        __syncthreads();
        sh[t] += u;
        __syncthreads();
    }
    if (i < N_NODES) {
        g_rowptr[i] = g_boff[blockIdx.x] + sh[t] - c;
        g_dinv[i]   = rsqrtf((float)c + 1.0f);
    }
}

// atomic-free fill: slot = rowptr[d] + eoff[e]
__global__ void k_fill(const void* __restrict__ src, const void* __restrict__ dst) {
    int e = blockIdx.x * blockDim.x + threadIdx.x;
    if (e >= N_EDGES) return;
    int is64 = g_idx64;
    int s = get_idx(src, e, is64);
    int d = get_idx(dst, e, is64);
    if ((unsigned)s >= (unsigned)N_NODES || (unsigned)d >= (unsigned)N_NODES) return;
    int pos = g_rowptr[d] + g_eoff[e];
    g_esrc [pos] = s;
    g_enorm[pos] = g_dinv[s] * g_dinv[d];
}

// ---------------- gather 1: agg1 = tf32(self + neighbors) of x ----------------
__global__ void k_gather1(const float4* __restrict__ x) {
    int wid = (blockIdx.x * blockDim.x + threadIdx.x) >> 5;
    if (wid >= N_NODES) return;
    int j = threadIdx.x & 31;
    float di = g_dinv[wid];
    float4 v0 = x[(size_t)wid * 32 + j];
    float s2 = di * di;
    float4 acc = make_float4(v0.x * s2, v0.y * s2, v0.z * s2, v0.w * s2);

    int i   = g_rowptr[wid];
    int end = g_rowptr[wid + 1];
    for (; i + 1 < end; i += 2) {
        int   s0 = __ldg(&g_esrc[i]),  s1 = __ldg(&g_esrc[i + 1]);
        float w0 = __ldg(&g_enorm[i]), w1 = __ldg(&g_enorm[i + 1]);
        float4 a = x[(size_t)s0 * 32 + j];
        float4 b = x[(size_t)s1 * 32 + j];
        acc.x += w0 * a.x + w1 * b.x;
        acc.y += w0 * a.y + w1 * b.y;
        acc.z += w0 * a.z + w1 * b.z;
        acc.w += w0 * a.w + w1 * b.w;
    }
    if (i < end) {
        int   s0 = __ldg(&g_esrc[i]);
        float w0 = __ldg(&g_enorm[i]);
        float4 a = x[(size_t)s0 * 32 + j];
        acc.x += w0 * a.x; acc.y += w0 * a.y;
        acc.z += w0 * a.z; acc.w += w0 * a.w;
    }
    g_agg1[(size_t)wid * 32 + j] =
        make_uint4(f2tf32(acc.x), f2tf32(acc.y), f2tf32(acc.z), f2tf32(acc.w));
}

// ---------------- gather 2 + fused pooling ----------------
__global__ void k_gather2(const void* __restrict__ batch, const float* __restrict__ b2) {
    int wid = (blockIdx.x * blockDim.x + threadIdx.x) >> 5;
    if (wid >= N_NODES) return;
    int j = threadIdx.x & 31;
    float di = g_dinv[wid];
    float4 v0 = g_m2[(size_t)wid * 32 + j];
    float s2 = di * di;
    float4 acc = make_float4(v0.x * s2, v0.y * s2, v0.z * s2, v0.w * s2);

    int i   = g_rowptr[wid];
    int end = g_rowptr[wid + 1];
    for (; i + 1 < end; i += 2) {
        int   s0 = __ldg(&g_esrc[i]),  s1 = __ldg(&g_esrc[i + 1]);
        float w0 = __ldg(&g_enorm[i]), w1 = __ldg(&g_enorm[i + 1]);
        float4 a = g_m2[(size_t)s0 * 32 + j];
        float4 b = g_m2[(size_t)s1 * 32 + j];
        acc.x += w0 * a.x + w1 * b.x;
        acc.y += w0 * a.y + w1 * b.y;
        acc.z += w0 * a.z + w1 * b.z;
        acc.w += w0 * a.w + w1 * b.w;
    }
    if (i < end) {
        int   s0 = __ldg(&g_esrc[i]);
        float w0 = __ldg(&g_enorm[i]);
        float4 a = g_m2[(size_t)s0 * 32 + j];
        acc.x += w0 * a.x; acc.y += w0 * a.y;
        acc.z += w0 * a.z; acc.w += w0 * a.w;
    }

    int b = get_idx(batch, wid, g_idx64);
    if ((unsigned)b >= (unsigned)N_GRAPHS) return;
    float4 bb = ((const float4*)b2)[j];
    acc.x = fmaxf(acc.x + bb.x, 0.f);
    acc.y = fmaxf(acc.y + bb.y, 0.f);
    acc.z = fmaxf(acc.z + bb.z, 0.f);
    acc.w = fmaxf(acc.w + bb.w, 0.f);
    red_add_v4(&g_pool[b * HID2 + j * 4], acc);
    if (j == 0) atomicAdd(&g_cnt[b], 1.0f);
}

// ---------------- GEMM: 3-stage cp.async pipeline, operands pre-tf32 ----------
// C[M,N] = A[M,K] @ B[K,N]. BM=128, BN=128, BK=16, NST=3 (dynamic smem 56.8KB).
template <int KDIM, int NDIM, bool RELU_BIAS, bool OUT_TF32>
__device__ __forceinline__ void gemm_pipe_body(const unsigned* __restrict__ A,
                                               const unsigned* __restrict__ B,
                                               const float* __restrict__ bias,
                                               void* __restrict__ Cout) {
    constexpr int BM = 128, BN = 128, BK = 16;
    constexpr int ASTR = 20;
    constexpr int BSTR = 136;
    constexpr int ATILE = BM * ASTR;                 // 2560
    constexpr int STAGE = ATILE + BK * BSTR;         // 4736 unsigned
    constexpr int KT = KDIM / BK;
    extern __shared__ unsigned shbuf[];              // 3 * STAGE

    const int t    = threadIdx.x;
    const int lane = t & 31;
    const int w    = t >> 5;
    const int mw   = w & 3;
    const int nw   = w >> 2;
    const int g    = lane >> 2;
    const int tg   = lane & 3;
    const int cRow = blockIdx.y * BM;
    const int cCol = blockIdx.x * BN;

    float acc[2][8][4];
    #pragma unroll
    for (int mt = 0; mt < 2; mt++)
        #pragma unroll
        for (int nt = 0; nt < 8; nt++)
            #pragma unroll
            for (int i = 0; i < 4; i++) acc[mt][nt][i] = 0.0f;

    auto load_tile = [&](int kt, int buf) {
        unsigned* as = shbuf + buf * STAGE;
        unsigned* bs = as + ATILE;
        int k0 = kt * BK;
        #pragma unroll
        for (int i = 0; i < 2; i++) {
            int fa  = t + 256 * i;
            int ar  = fa >> 2;
            int ac4 = fa & 3;
            int sz  = (cRow + ar < N_NODES) ? 16 : 0;
            cp_async16(&as[ar * ASTR + ac4 * 4],
                       A + (size_t)(cRow + ar) * KDIM + k0 + ac4 * 4, sz);
            int br  = fa >> 5;
            int bc4 = fa & 31;
            cp_async16(&bs[br * BSTR + bc4 * 4],
                       B + (size_t)(k0 + br) * NDIM + cCol + bc4 * 4, 16);
        }
        cp_commit();
    };

    load_tile(0, 0);
    load_tile(1, 1);
    for (int kt = 0; kt < KT; kt++) {
        if (kt + 1 < KT) cp_wait<1>();
        else             cp_wait<0>();
        __syncthreads();
        const unsigned* as = shbuf + (kt % 3) * STAGE;
        const unsigned* bs = as + ATILE;
        #pragma unroll
        for (int kk = 0; kk < BK; kk += 8) {
            unsigned a[2][4];
            #pragma unroll
            for (int mt = 0; mt < 2; mt++) {
                int r0 = mw * 32 + mt * 16 + g;
                a[mt][0] = as[r0 * ASTR + kk + tg];
                a[mt][1] = as[(r0 + 8) * ASTR + kk + tg];
                a[mt][2] = as[r0 * ASTR + kk + tg + 4];
                a[mt][3] = as[(r0 + 8) * ASTR + kk + tg + 4];
            }
            #pragma unroll
            for (int nt = 0; nt < 8; nt++) {
                unsigned b[2];
                int c0 = nw * 64 + nt * 8 + g;
                b[0] = bs[(kk + tg)     * BSTR + c0];
                b[1] = bs[(kk + tg + 4) * BSTR + c0];
                mma_tf32(acc[0][nt], a[0], b);
                mma_tf32(acc[1][nt], a[1], b);
            }
        }
        __syncthreads();
        if (kt + 2 < KT) load_tile(kt + 2, (kt + 2) % 3);
    }

    #pragma unroll
    for (int mt = 0; mt < 2; mt++) {
        int rBase = cRow + mw * 32 + mt * 16 + g;
        #pragma unroll
        for (int nt = 0; nt < 8; nt++) {
            int c = cCol + nw * 64 + nt * 8 + 2 * tg;
            float f0 = acc[mt][nt][0], f1 = acc[mt][nt][1];
            float f2 = acc[mt][nt][2], f3 = acc[mt][nt][3];
            if (RELU_BIAS) {
                float2 bb = *(const float2*)(bias + c);
                f0 = fmaxf(f0 + bb.x, 0.f); f1 = fmaxf(f1 + bb.y, 0.f);
                f2 = fmaxf(f2 + bb.x, 0.f); f3 = fmaxf(f3 + bb.y, 0.f);
            }
            if (OUT_TF32) {
                unsigned* C = (unsigned*)Cout;
                if (rBase < N_NODES) {
                    uint2 u = make_uint2(f2tf32(f0), f2tf32(f1));
                    *(uint2*)(C + (size_t)rBase * NDIM + c) = u;
                }
                if (rBase + 8 < N_NODES) {
                    uint2 u = make_uint2(f2tf32(f2), f2tf32(f3));
                    *(uint2*)(C + (size_t)(rBase + 8) * NDIM + c) = u;
                }
            } else {
                float* C = (float*)Cout;
                if (rBase < N_NODES)
                    *(float2*)(C + (size_t)rBase * NDIM + c) = make_float2(f0, f1);
                if (rBase + 8 < N_NODES)
                    *(float2*)(C + (size_t)(rBase + 8) * NDIM + c) = make_float2(f2, f3);
            }
        }
    }
}

__global__ void __launch_bounds__(256) k_gemm1(const float* __restrict__ b1) {
    gemm_pipe_body<IN_DIM, HID, true, true>((const unsigned*)g_agg1, g_w1t, b1, g_h1);
}

__global__ void __launch_bounds__(256) k_gemm2() {
    gemm_pipe_body<HID, HID2, false, false>(g_h1, g_w2t, nullptr, (float*)g_m2);
}

// ---------------- fc tail ----------------
__global__ void k_out(const float* __restrict__ Wfc, const float* __restrict__ bfc,
                      float* __restrict__ out) {
    int t = threadIdx.x;
    if (t >= N_GRAPHS * OUT_DIM) return;
    int g = t >> 2;
    int o = t & 3;
    float inv = 1.0f / fmaxf(g_cnt[g], 1.0f);
    float s = 0.0f;
    #pragma unroll 16
    for (int k = 0; k < HID2; k++)
        s = fmaf(g_pool[g * HID2 + k], Wfc[k * OUT_DIM + o], s);
    out[t] = s * inv + bfc[o];
}

// ---------------- launch ----------------
extern "C" void kernel_launch(void* const* d_in, const int* in_sizes, int n_in,
                              void* d_out, int out_size) {
    int ix = -1, isrc = -1, idst = -1, ibatch = -1, iW1 = -1, iW2 = -1;
    int ib1 = -1, ib2 = -1, iWfc = -1, ibfc = -1;
    for (int i = 0; i < n_in; i++) {
        int s = in_sizes[i];
        if      (s == N_NODES * IN_DIM)  ix = i;
        else if (s == N_EDGES)           { if (isrc < 0) isrc = i; else idst = i; }
        else if (s == N_NODES)           ibatch = i;
        else if (s == IN_DIM * HID)      { if (iW1 < 0) iW1 = i; else iW2 = i; }
        else if (s == HID)               ib1 = i;
        else if (s == HID2)              ib2 = i;
        else if (s == HID2 * OUT_DIM)    iWfc = i;
        else if (s == OUT_DIM)           ibfc = i;
    }
    if (in_sizes[0] != N_NODES * IN_DIM) { int tmp = isrc; isrc = idst; idst = tmp; }

    const float* x     = (const float*)d_in[ix];
    const void*  src   = d_in[isrc];
    const void*  dst   = d_in[idst];
    const void*  batch = d_in[ibatch];
    const float* W1    = (const float*)d_in[iW1];
    const float* b1    = (const float*)d_in[ib1];
    const float* W2    = (const float*)d_in[iW2];
    const float* b2    = (const float*)d_in[ib2];
    const float* Wfc   = (const float*)d_in[iWfc];
    const float* bfc   = (const float*)d_in[ibfc];
    float* out = (float*)d_out;

    const int SMEM_GEMM = 3 * (128 * 20 + 16 * 136) * 4;   // 56,832 B
    cudaFuncSetAttribute(k_gemm1, cudaFuncAttributeMaxDynamicSharedMemorySize, SMEM_GEMM);
    cudaFuncSetAttribute(k_gemm2, cudaFuncAttributeMaxDynamicSharedMemorySize, SMEM_GEMM);

    const int TPB = 256;
    const int nodeBlocks = (N_NODES + TPB - 1) / TPB;
    const int edgeBlocks = (N_EDGES + TPB - 1) / TPB;
    const int nvecBlocks = (N_NODES * 32 + TPB - 1) / TPB;

    // fused setup (detect + weight cvt + zero count/pool)
    k_setup<<<nodeBlocks, TPB>>>((const int*)src, W1, W2);

    // CSR build: hist(+local offsets) -> two-level scan -> atomic-free fill
    k_hist    <<<edgeBlocks, TPB>>>(dst);
    k_blocksum<<<SCAN_BLKS, SCAN_TPB>>>();
    k_scanpart<<<1, 256>>>();
    k_rowptr  <<<SCAN_BLKS, SCAN_TPB>>>();
    k_fill    <<<edgeBlocks, TPB>>>(src, dst);

    // layer 1
    k_gather1<<<nvecBlocks, TPB>>>((const float4*)x);
    {
        dim3 grid(HID / 128, (N_NODES + 127) / 128);
        k_gemm1<<<grid, 256, SMEM_GEMM>>>(b1);
    }

    // layer 2 (+fused pool)
    {
        dim3 grid(HID2 / 128, (N_NODES + 127) / 128);
        k_gemm2<<<grid, 256, SMEM_GEMM>>>();
    }
    k_gather2<<<nvecBlocks, TPB>>>(batch, b2);

    // fc
    k_out<<<1, N_GRAPHS * OUT_DIM>>>(Wfc, bfc, out);
}

// round 14
// speedup vs baseline: 1.9225x; 1.1830x over previous
#include <cuda_runtime.h>
#include <cuda_fp16.h>

// ---------------- problem constants ----------------
#define N_NODES  50000
#define N_EDGES  640000
#define N_GRAPHS 64
#define IN_DIM   128
#define HID      256
#define HID2     128   // HID/2
#define OUT_DIM  4

#define SCAN_TPB   256
#define SCAN_BLKS  ((N_NODES + SCAN_TPB - 1) / SCAN_TPB)   // 196

// ---------------- scratch (static device arrays; no allocation) ----------------
// RULE: symbols referenced ONLY inside device code (host shadow + ATS trap).
__device__ float          g_dinv[N_NODES];            // rsqrt(deg+1)
__device__ int            g_count [N_NODES];
__device__ int            g_rowptr[N_NODES + 1];
__device__ int            g_bsum [SCAN_BLKS];
__device__ int            g_boff [SCAN_BLKS];
__device__ int            g_esrc [N_EDGES];
__device__ int            g_eoff [N_EDGES];
__device__ float          g_enorm[N_EDGES];
__device__ unsigned short g_xh  [N_NODES * IN_DIM];   // x as fp16
__device__ unsigned short g_w1h [HID  * IN_DIM];      // W1^T [N=256][K=128] fp16
__device__ unsigned short g_w2h [HID2 * HID];         // W2^T [N=128][K=256] fp16
__device__ unsigned short g_a1h [N_NODES * IN_DIM];   // aggregated x, fp16
__device__ unsigned short g_h1h [N_NODES * HID];      // relu(a1@W1+b1), fp16
__device__ unsigned short g_m2h [N_NODES * HID2];     // h1@W2, fp16
__device__ float          g_pool[N_GRAPHS * HID2];
__device__ float          g_cnt [N_GRAPHS];
__device__ int            g_idx64;

// ---------------- helpers ----------------
__device__ __forceinline__ void red_add_v4(float* addr, float4 v) {
    asm volatile("red.global.add.v4.f32 [%0], {%1,%2,%3,%4};"
                 :: "l"(addr), "f"(v.x), "f"(v.y), "f"(v.z), "f"(v.w)
                 : "memory");
}

__device__ __forceinline__ int get_idx(const void* p, int i, int is64) {
    long long v;
    if (is64) v = __ldg(((const long long*)p) + i);
    else      v = __ldg(((const int*)p) + i);
    return (int)v;
}

// m16n8k16 fp16 MMA, fp32 accumulate (D += A*B), row.col
__device__ __forceinline__ void mma_f16(float* d, const unsigned* a, const unsigned* b) {
    asm volatile(
        "mma.sync.aligned.m16n8k16.row.col.f32.f16.f16.f32 "
        "{%0,%1,%2,%3}, {%4,%5,%6,%7}, {%8,%9}, {%0,%1,%2,%3};"
        : "+f"(d[0]), "+f"(d[1]), "+f"(d[2]), "+f"(d[3])
        : "r"(a[0]), "r"(a[1]), "r"(a[2]), "r"(a[3]), "r"(b[0]), "r"(b[1]));
}

__device__ __forceinline__ void cp_async16(void* smem, const void* gmem, int szbytes) {
    unsigned saddr = (unsigned)__cvta_generic_to_shared(smem);
    asm volatile("cp.async.cg.shared.global [%0], [%1], 16, %2;"
                 :: "r"(saddr), "l"(gmem), "r"(szbytes));
}
__device__ __forceinline__ void cp_commit() {
    asm volatile("cp.async.commit_group;");
}
template <int N>
__device__ __forceinline__ void cp_wait() {
    asm volatile("cp.async.wait_group %0;" :: "n"(N));
}

__device__ __forceinline__ float2 h2f(unsigned u) {
    __half2 h = *reinterpret_cast<__half2*>(&u);
    return __half22float2(h);
}
__device__ __forceinline__ unsigned f2h2(float a, float b) {
    __half2 h = __floats2half2_rn(a, b);
    return *reinterpret_cast<unsigned*>(&h);
}

// ---------------- fused setup: detect dtype, cvt x + weights, zero ----------
__global__ void k_setup(const int* __restrict__ srcprobe, const float* __restrict__ x,
                        const float* __restrict__ W1, const float* __restrict__ W2) {
    int tid = blockIdx.x * blockDim.x + threadIdx.x;
    int nth = gridDim.x * blockDim.x;

    // x -> fp16 (float4 granularity: 1.6M iters)
    for (int i = tid; i < N_NODES * IN_DIM / 4; i += nth) {
        float4 v = ((const float4*)x)[i];
        uint2 o = make_uint2(f2h2(v.x, v.y), f2h2(v.z, v.w));
        ((uint2*)g_xh)[i] = o;
    }
    // W1^T [n][k], n<256, k<128
    for (int i = tid; i < IN_DIM * HID; i += nth) {
        int n = i >> 7, k = i & 127;
        g_w1h[n * IN_DIM + k] = __half_as_ushort(__float2half_rn(W1[k * HID + n]));
    }
    // W2^T [n][k], n<128, k<256
    for (int i = tid; i < HID * HID2; i += nth) {
        int n = i >> 8, k = i & 255;
        g_w2h[n * HID + k] = __half_as_ushort(__float2half_rn(W2[k * HID2 + n]));
    }
    if (tid < N_NODES) g_count[tid] = 0;
    if (tid < N_GRAPHS * HID2) g_pool[tid] = 0.0f;
    if (tid < N_GRAPHS) g_cnt[tid] = 0.0f;
    if (blockIdx.x == 0 && threadIdx.x < 32) {
        int lane = threadIdx.x;
        int nz = 0;
        for (int k = lane; k < 4096; k += 32)
            if (srcprobe[2 * k + 1] != 0) nz = 1;
        unsigned m = __ballot_sync(0xffffffffu, nz);
        if (lane == 0) g_idx64 = (m == 0u) ? 1 : 0;
    }
}

// ---------------- CSR build ----------------
__global__ void k_hist(const void* __restrict__ dst) {
    int e = blockIdx.x * blockDim.x + threadIdx.x;
    if (e < N_EDGES) {
        int d = get_idx(dst, e, g_idx64);
        if ((unsigned)d < (unsigned)N_NODES)
            g_eoff[e] = atomicAdd(&g_count[d], 1);
    }
}

__global__ void __launch_bounds__(SCAN_TPB) k_blocksum() {
    __shared__ int sh[SCAN_TPB / 32];
    int i = blockIdx.x * SCAN_TPB + threadIdx.x;
    int v = (i < N_NODES) ? g_count[i] : 0;
    #pragma unroll
    for (int o = 16; o > 0; o >>= 1) v += __shfl_down_sync(0xffffffffu, v, o);
    if ((threadIdx.x & 31) == 0) sh[threadIdx.x >> 5] = v;
    __syncthreads();
    if (threadIdx.x < SCAN_TPB / 32) {
        int s = sh[threadIdx.x];
        #pragma unroll
        for (int o = SCAN_TPB / 64; o > 0; o >>= 1)
            s += __shfl_down_sync(0xffffffffu, s, o);
        if (threadIdx.x == 0) g_bsum[blockIdx.x] = s;
    }
}

__global__ void __launch_bounds__(256) k_scanpart() {
    __shared__ int sh[256];
    int t = threadIdx.x;
    int v = (t < SCAN_BLKS) ? g_bsum[t] : 0;
    sh[t] = v;
    __syncthreads();
    for (int d = 1; d < 256; d <<= 1) {
        int u = (t >= d) ? sh[t - d] : 0;
        __syncthreads();
        sh[t] += u;
        __syncthreads();
    }
    if (t < SCAN_BLKS) g_boff[t] = sh[t] - v;
    if (t == 0) g_rowptr[N_NODES] = N_EDGES;
}

__global__ void __launch_bounds__(SCAN_TPB) k_rowptr() {
    __shared__ int sh[SCAN_TPB];
    int t = threadIdx.x;
    int i = blockIdx.x * SCAN_TPB + t;
    int c = (i < N_NODES) ? g_count[i] : 0;
    sh[t] = c;
    __syncthreads();
    for (int d = 1; d < SCAN_TPB; d <<= 1) {
        int u = (t >= d) ? sh[t - d] : 0;
        __syncthreads();
        sh[t] += u;
        __syncthreads();
    }
    if (i < N_NODES) {
        g_rowptr[i] = g_boff[blockIdx.x] + sh[t] - c;
        g_dinv[i]   = rsqrtf((float)c + 1.0f);
    }
}

__global__ void k_fill(const void* __restrict__ src, const void* __restrict__ dst) {
    int e = blockIdx.x * blockDim.x + threadIdx.x;
    if (e >= N_EDGES) return;
    int is64 = g_idx64;
    int s = get_idx(src, e, is64);
    int d = get_idx(dst, e, is64);
    if ((unsigned)s >= (unsigned)N_NODES || (unsigned)d >= (unsigned)N_NODES) return;
    int pos = g_rowptr[d] + g_eoff[e];
    g_esrc [pos] = s;
    g_enorm[pos] = g_dinv[s] * g_dinv[d];
}

// ---------------- gather core (fp16 feature table, fp32 accumulate) --------
// One warp per destination node; lane j owns 4 features (uint2 = 4 halfs).
__device__ __forceinline__ float4 gather_acc(const uint2* __restrict__ ft, int wid, int j) {
    float di = g_dinv[wid];
    float s2 = di * di;
    uint2 u0 = ft[(size_t)wid * 32 + j];
    float2 p0 = h2f(u0.x), p1 = h2f(u0.y);
    float4 acc = make_float4(p0.x * s2, p0.y * s2, p1.x * s2, p1.y * s2);

    int i   = g_rowptr[wid];
    int end = g_rowptr[wid + 1];
    for (; i + 1 < end; i += 2) {
        int   s0 = __ldg(&g_esrc[i]),  s1 = __ldg(&g_esrc[i + 1]);
        float w0 = __ldg(&g_enorm[i]), w1 = __ldg(&g_enorm[i + 1]);
        uint2 ua = ft[(size_t)s0 * 32 + j];
        uint2 ub = ft[(size_t)s1 * 32 + j];
        float2 a0 = h2f(ua.x), a1 = h2f(ua.y);
        float2 b0 = h2f(ub.x), b1 = h2f(ub.y);
        acc.x += w0 * a0.x + w1 * b0.x;
        acc.y += w0 * a0.y + w1 * b0.y;
        acc.z += w0 * a1.x + w1 * b1.x;
        acc.w += w0 * a1.y + w1 * b1.y;
    }
    if (i < end) {
        int   s0 = __ldg(&g_esrc[i]);
        float w0 = __ldg(&g_enorm[i]);
        uint2 ua = ft[(size_t)s0 * 32 + j];
        float2 a0 = h2f(ua.x), a1 = h2f(ua.y);
        acc.x += w0 * a0.x; acc.y += w0 * a0.y;
        acc.z += w0 * a1.x; acc.w += w0 * a1.y;
    }
    return acc;
}

__global__ void k_gather1() {
    int wid = (blockIdx.x * blockDim.x + threadIdx.x) >> 5;
    if (wid >= N_NODES) return;
    int j = threadIdx.x & 31;
    float4 acc = gather_acc((const uint2*)g_xh, wid, j);
    ((uint2*)g_a1h)[(size_t)wid * 32 + j] =
        make_uint2(f2h2(acc.x, acc.y), f2h2(acc.z, acc.w));
}

// gather2 + fused pooling: pool[batch[d]] += relu(agg2[d] + b2)
__global__ void k_gather2(const void* __restrict__ batch, const float* __restrict__ b2) {
    int wid = (blockIdx.x * blockDim.x + threadIdx.x) >> 5;
    if (wid >= N_NODES) return;
    int j = threadIdx.x & 31;
    float4 acc = gather_acc((const uint2*)g_m2h, wid, j);

    int b = get_idx(batch, wid, g_idx64);
    if ((unsigned)b >= (unsigned)N_GRAPHS) return;
    float4 bb = ((const float4*)b2)[j];
    acc.x = fmaxf(acc.x + bb.x, 0.f);
    acc.y = fmaxf(acc.y + bb.y, 0.f);
    acc.z = fmaxf(acc.z + bb.z, 0.f);
    acc.w = fmaxf(acc.w + bb.w, 0.f);
    red_add_v4(&g_pool[b * HID2 + j * 4], acc);
    if (j == 0) atomicAdd(&g_cnt[b], 1.0f);
}

// ---------------- GEMM: fp16 m16n8k16 mma, cp.async double-buffered --------
// C[M,N] = A[M,K] @ Bt[N,K]^T (+bias,relu). BM=128, BN=128, BK=32.
// 8 warps 4(m)x2(n); warp tile 32m x 64n. Shared stride 40 halfs -> conflict-free.
template <int KDIM, int NDIM, bool RELU_BIAS>
__device__ __forceinline__ void gemm_f16_body(const unsigned short* __restrict__ A,
                                              const unsigned short* __restrict__ Bt,
                                              const float* __restrict__ bias,
                                              unsigned short* __restrict__ C) {
    constexpr int BM = 128, BN = 128, BK = 32;
    constexpr int STR = 40;                    // halfs
    constexpr int KT  = KDIM / BK;
    __shared__ unsigned short As[2][BM * STR]; // 10240 B each
    __shared__ unsigned short Bs[2][BN * STR];

    const int t    = threadIdx.x;
    const int lane = t & 31;
    const int w    = t >> 5;
    const int mw   = w & 3;
    const int nw   = w >> 2;
    const int g    = lane >> 2;
    const int tg   = lane & 3;
    const int cRow = blockIdx.y * BM;
    const int cCol = blockIdx.x * BN;

    float acc[2][8][4];
    #pragma unroll
    for (int mt = 0; mt < 2; mt++)
        #pragma unroll
        for (int nt = 0; nt < 8; nt++)
            #pragma unroll
            for (int i = 0; i < 4; i++) acc[mt][nt][i] = 0.0f;

    // tile loader: A 128 rows x 64B (4 chunks) + B 128 rows x 64B -> 4 chunks/thread
    auto load_tile = [&](int kt, int buf) {
        int k0 = kt * BK;
        #pragma unroll
        for (int i = 0; i < 2; i++) {
            int f  = t + 256 * i;           // 0..511
            int r  = f >> 2;                 // row 0..127
            int ck = f & 3;                  // 16B chunk = 8 halfs
            int sz = (cRow + r < N_NODES) ? 16 : 0;
            cp_async16(&As[buf][r * STR + ck * 8],
                       A + (size_t)(cRow + r) * KDIM + k0 + ck * 8, sz);
            cp_async16(&Bs[buf][r * STR + ck * 8],
                       Bt + (size_t)(cCol + r) * KDIM + k0 + ck * 8, 16);
        }
        cp_commit();
    };

    load_tile(0, 0);
    for (int kt = 0; kt < KT; kt++) {
        if (kt + 1 < KT) { load_tile(kt + 1, (kt + 1) & 1); cp_wait<1>(); }
        else             { cp_wait<0>(); }
        __syncthreads();
        const unsigned short* as = As[kt & 1];
        const unsigned short* bs = Bs[kt & 1];
        #pragma unroll
        for (int kk = 0; kk < BK; kk += 16) {
            unsigned a[2][4];
            #pragma unroll
            for (int mt = 0; mt < 2; mt++) {
                int r0 = mw * 32 + mt * 16 + g;
                a[mt][0] = *(const unsigned*)&as[r0 * STR + kk + 2 * tg];
                a[mt][1] = *(const unsigned*)&as[(r0 + 8) * STR + kk + 2 * tg];
                a[mt][2] = *(const unsigned*)&as[r0 * STR + kk + 2 * tg + 8];
                a[mt][3] = *(const unsigned*)&as[(r0 + 8) * STR + kk + 2 * tg + 8];
            }
            #pragma unroll
            for (int nt = 0; nt < 8; nt++) {
                int n = nw * 64 + nt * 8 + g;
                unsigned b[2];
                b[0] = *(const unsigned*)&bs[n * STR + kk + 2 * tg];
                b[1] = *(const unsigned*)&bs[n * STR + kk + 2 * tg + 8];
                mma_f16(acc[0][nt], a[0], b);
                mma_f16(acc[1][nt], a[1], b);
            }
        }
        __syncthreads();
    }

    #pragma unroll
    for (int mt = 0; mt < 2; mt++) {
        int rBase = cRow + mw * 32 + mt * 16 + g;
        #pragma unroll
        for (int nt = 0; nt < 8; nt++) {
            int c = cCol + nw * 64 + nt * 8 + 2 * tg;
            float f0 = acc[mt][nt][0], f1 = acc[mt][nt][1];
            float f2 = acc[mt][nt][2], f3 = acc[mt][nt][3];
            if (RELU_BIAS) {
                float2 bb = *(const float2*)(bias + c);
                f0 = fmaxf(f0 + bb.x, 0.f); f1 = fmaxf(f1 + bb.y, 0.f);
                f2 = fmaxf(f2 + bb.x, 0.f); f3 = fmaxf(f3 + bb.y, 0.f);
            }
            if (rBase < N_NODES)
                *(unsigned*)(C + (size_t)rBase * NDIM + c) = f2h2(f0, f1);
            if (rBase + 8 < N_NODES)
                *(unsigned*)(C + (size_t)(rBase + 8) * NDIM + c) = f2h2(f2, f3);
        }
    }
}

__global__ void __launch_bounds__(256) k_gemm1(const float* __restrict__ b1) {
    gemm_f16_body<IN_DIM, HID, true>(g_a1h, g_w1h, b1, g_h1h);
}

__global__ void __launch_bounds__(256) k_gemm2() {
    gemm_f16_body<HID, HID2, false>(g_h1h, g_w2h, nullptr, g_m2h);
}

// ---------------- fc tail ----------------
__global__ void k_out(const float* __restrict__ Wfc, const float* __restrict__ bfc,
                      float* __restrict__ out) {
    int t = threadIdx.x;
    if (t >= N_GRAPHS * OUT_DIM) return;
    int g = t >> 2;
    int o = t & 3;
    float inv = 1.0f / fmaxf(g_cnt[g], 1.0f);
    float s = 0.0f;
    #pragma unroll 16
    for (int k = 0; k < HID2; k++)
        s = fmaf(g_pool[g * HID2 + k], Wfc[k * OUT_DIM + o], s);
    out[t] = s * inv + bfc[o];
}

// ---------------- launch ----------------
extern "C" void kernel_launch(void* const* d_in, const int* in_sizes, int n_in,
                              void* d_out, int out_size) {
    int ix = -1, isrc = -1, idst = -1, ibatch = -1, iW1 = -1, iW2 = -1;
    int ib1 = -1, ib2 = -1, iWfc = -1, ibfc = -1;
    for (int i = 0; i < n_in; i++) {
        int s = in_sizes[i];
        if      (s == N_NODES * IN_DIM)  ix = i;
        else if (s == N_EDGES)           { if (isrc < 0) isrc = i; else idst = i; }
        else if (s == N_NODES)           ibatch = i;
        else if (s == IN_DIM * HID)      { if (iW1 < 0) iW1 = i; else iW2 = i; }
        else if (s == HID)               ib1 = i;
        else if (s == HID2)              ib2 = i;
        else if (s == HID2 * OUT_DIM)    iWfc = i;
        else if (s == OUT_DIM)           ibfc = i;
    }
    if (in_sizes[0] != N_NODES * IN_DIM) { int tmp = isrc; isrc = idst; idst = tmp; }

    const float* x     = (const float*)d_in[ix];
    const void*  src   = d_in[isrc];
    const void*  dst   = d_in[idst];
    const void*  batch = d_in[ibatch];
    const float* W1    = (const float*)d_in[iW1];
    const float* b1    = (const float*)d_in[ib1];
    const float* W2    = (const float*)d_in[iW2];
    const float* b2    = (const float*)d_in[ib2];
    const float* Wfc   = (const float*)d_in[iWfc];
    const float* bfc   = (const float*)d_in[ibfc];
    float* out = (float*)d_out;

    const int TPB = 256;
    const int edgeBlocks = (N_EDGES + TPB - 1) / TPB;
    const int nvecBlocks = (N_NODES * 32 + TPB - 1) / TPB;

    // fused setup (detect + x/weight cvt + transposes + zero)
    k_setup<<<1600, TPB>>>((const int*)src, x, W1, W2);

    // CSR build
    k_hist    <<<edgeBlocks, TPB>>>(dst);
    k_blocksum<<<SCAN_BLKS, SCAN_TPB>>>();
    k_scanpart<<<1, 256>>>();
    k_rowptr  <<<SCAN_BLKS, SCAN_TPB>>>();
    k_fill    <<<edgeBlocks, TPB>>>(src, dst);

    // layer 1
    k_gather1<<<nvecBlocks, TPB>>>();
    {
        dim3 grid(HID / 128, (N_NODES + 127) / 128);
        k_gemm1<<<grid, 256>>>(b1);
    }

    // layer 2 (+fused pool)
    {
        dim3 grid(HID2 / 128, (N_NODES + 127) / 128);
        k_gemm2<<<grid, 256>>>();
    }
    k_gather2<<<nvecBlocks, TPB>>>(batch, b2);

    // fc
    k_out<<<1, N_GRAPHS * OUT_DIM>>>(Wfc, bfc, out);
}